// round 7
// baseline (speedup 1.0000x reference)
#include <cuda_runtime.h>
#include <math.h>

#define NN   16384
#define KN   16
#define DD   128
#define HH   8
#define LL   2
#define EE   32
#define DFFC 512

// ---------- packed f32x2 helpers (Blackwell FFMA2 path) ----------
__device__ __forceinline__ unsigned long long pk2(float lo, float hi){
    unsigned long long r;
    asm("mov.b64 %0, {%1, %2};" : "=l"(r) : "f"(lo), "f"(hi));
    return r;
}
__device__ __forceinline__ void upk2(unsigned long long v, float& lo, float& hi){
    asm("mov.b64 {%0, %1}, %2;" : "=f"(lo), "=f"(hi) : "l"(v));
}
__device__ __forceinline__ unsigned long long fma2(unsigned long long a, unsigned long long b,
                                                   unsigned long long c){
    unsigned long long d;
    asm("fma.rn.f32x2 %0, %1, %2, %3;" : "=l"(d) : "l"(a), "l"(b), "l"(c));
    return d;
}

__device__ __forceinline__ float gelu_tanh(float x){
    // jax.nn.gelu(approximate=True): 0.5x(1+tanh(sqrt(2/pi)(x+0.044715 x^3)))
    float u = 0.7978845608028654f * fmaf(0.044715f * x, x * x, x);
    return 0.5f * x * (1.0f + tanhf(u));
}

// out16[r] += sum_d A[r][d] * W[d][c]   (A in shared [16][DIN], W global [DIN][C])
// Packed: even/odd d accumulated in the two halves of a b64 register.
// Weight loads for iteration i+1 are prefetched during iteration i.
template<int DIN, int C>
__device__ __forceinline__ void gemm16(const float* A, const float* __restrict__ W,
                                       int c, float* out16){
    unsigned long long acc[16];
    #pragma unroll
    for (int r = 0; r < 16; ++r) acc[r] = 0ull;
    const ulonglong2* A2 = reinterpret_cast<const ulonglong2*>(A);

    const float* wp = W + c;
    float w0 = __ldg(wp);
    float w1 = __ldg(wp + C);
    float w2 = __ldg(wp + 2 * C);
    float w3 = __ldg(wp + 3 * C);

    #pragma unroll 2
    for (int d4 = 0; d4 < DIN / 4; ++d4){
        unsigned long long wA = pk2(w0, w1);
        unsigned long long wB = pk2(w2, w3);
        if (d4 + 1 < DIN / 4){                      // prefetch next 4 weights
            const float* wn = W + (d4 + 1) * 4 * C + c;
            w0 = __ldg(wn);
            w1 = __ldg(wn + C);
            w2 = __ldg(wn + 2 * C);
            w3 = __ldg(wn + 3 * C);
        }
        #pragma unroll
        for (int r = 0; r < 16; ++r){
            ulonglong2 fv = A2[r * (DIN / 4) + d4];   // LDS.128 -> two b64 packs
            acc[r] = fma2(fv.x, wA, acc[r]);
            acc[r] = fma2(fv.y, wB, acc[r]);
        }
    }
    #pragma unroll
    for (int r = 0; r < 16; ++r){
        float lo, hi; upk2(acc[r], lo, hi);
        out16[r] += lo + hi;
    }
}

// LayerNorm over 128 columns of 16 rows; a[16] holds this thread's column c of
// each row (already includes residual). Writes normalized result back to fs.
__device__ __forceinline__ void ln16(float* fs, float a[16], int c,
                                     const float* __restrict__ g,
                                     const float* __restrict__ b,
                                     float* part_s, float* part_s2,
                                     float* mean_s, float* rstd_s)
{
    #pragma unroll
    for (int r = 0; r < 16; ++r) fs[r * DD + c] = a[r];
    __syncthreads();
    {
        int gg = c >> 4, rr = c & 15;
        float s = 0.f, s2 = 0.f;
        #pragma unroll
        for (int j = 0; j < 16; ++j){
            float v = fs[rr * DD + gg * 16 + j];
            s += v; s2 = fmaf(v, v, s2);
        }
        part_s[rr * 8 + gg] = s; part_s2[rr * 8 + gg] = s2;
    }
    __syncthreads();
    if (c < 16){
        float su = 0.f, su2 = 0.f;
        #pragma unroll
        for (int j = 0; j < 8; ++j){ su += part_s[c * 8 + j]; su2 += part_s2[c * 8 + j]; }
        float mean = su * (1.f / 128.f);
        float var  = su2 * (1.f / 128.f) - mean * mean;
        mean_s[c] = mean; rstd_s[c] = rsqrtf(var + 1e-5f);
    }
    __syncthreads();
    float gc = g[c], bc = b[c];
    #pragma unroll
    for (int r = 0; r < 16; ++r)
        fs[r * DD + c] = (a[r] - mean_s[r]) * rstd_s[r] * gc + bc;
    __syncthreads();
}

__global__ __launch_bounds__(128, 4)
void tgn_fused_kernel(
    const float* __restrict__ node_h,   const int*   __restrict__ src_idx,
    const float* __restrict__ edge_feat,const float* __restrict__ t_in,
    const float* __restrict__ t_now,
    const float* __restrict__ edge_fc_w,const float* __restrict__ edge_fc_b,
    const float* __restrict__ basis_freq,const float* __restrict__ phase,
    const float* __restrict__ wq, const float* __restrict__ wk, const float* __restrict__ wv,
    const float* __restrict__ attn_fc_w, const float* __restrict__ attn_fc_b,
    const float* __restrict__ attn_ln_g, const float* __restrict__ attn_ln_b,
    const float* __restrict__ ffn_w1, const float* __restrict__ ffn_b1,
    const float* __restrict__ ffn_w2, const float* __restrict__ ffn_b2,
    const float* __restrict__ ffn_ln_g, const float* __restrict__ ffn_ln_b,
    const float* __restrict__ f2n_w, const float* __restrict__ f2n_b,
    const float* __restrict__ fin_g, const float* __restrict__ fin_b,
    float* __restrict__ out)
{
    __shared__ __align__(16) float fs[KN * DD];        // 2048 f : mailbox f
    __shared__ __align__(16) float big[KN * DFFC];     // 8192 f : q|k|v|attn-out, then hid
    __shared__ __align__(16) float ef[KN * EE];        // 512 f  : edge features
    __shared__ float part_s[16 * 8], part_s2[16 * 8];
    __shared__ float mean_s[16], rstd_s[16];
    __shared__ float pool[DD];
    __shared__ float t_sh[KN];
    __shared__ int   src_sh[KN];
    __shared__ float red[8];

    const int n = blockIdx.x;
    const int c = threadIdx.x;          // output column, 0..127

    float* qs  = big;
    float* ksm = big + 2048;
    float* vsm = big + 4096;
    float* tmp = big + 6144;

    // ---- stage edge features / timestamps / source indices ----
    {
        const float* efg = edge_feat + (size_t)n * KN * EE;
        #pragma unroll
        for (int j = 0; j < 4; ++j) ef[c + j * 128] = efg[c + j * 128];
        if (c < KN){ t_sh[c] = t_in[n * KN + c]; src_sh[c] = src_idx[n * KN + c]; }
    }
    __syncthreads();

    // ---- message: z = node_h[src] + gelu(edge@W+b) + cos((tnow-t)*freq + phase) ----
    {
        float vals[16];
        float eb = edge_fc_b[c];
        #pragma unroll
        for (int r = 0; r < 16; ++r) vals[r] = eb;
        #pragma unroll 4
        for (int e = 0; e < EE; ++e){
            float w = __ldg(edge_fc_w + e * DD + c);
            #pragma unroll
            for (int r = 0; r < 16; ++r) vals[r] = fmaf(ef[r * EE + e], w, vals[r]);
        }
        float fr = basis_freq[c], ph = phase[c], tn = t_now[0];
        #pragma unroll
        for (int r = 0; r < 16; ++r){
            float g  = gelu_tanh(vals[r]);
            float te = cosf((tn - t_sh[r]) * fr + ph);
            fs[r * DD + c] = node_h[(size_t)src_sh[r] * DD + c] + g + te;
        }
    }
    __syncthreads();

    // ---- transformer layers ----
    for (int layer = 0; layer < LL; ++layer){
        const float* Wq = wq + layer * DD * DD;
        const float* Wk = wk + layer * DD * DD;
        const float* Wv = wv + layer * DD * DD;

        // QKV projections (no bias)
        {
            float a[16];
            #pragma unroll
            for (int r = 0; r < 16; ++r) a[r] = 0.f;
            gemm16<DD, DD>(fs, Wq, c, a);
            #pragma unroll
            for (int r = 0; r < 16; ++r) qs[r * DD + c] = a[r];
        }
        {
            float a[16];
            #pragma unroll
            for (int r = 0; r < 16; ++r) a[r] = 0.f;
            gemm16<DD, DD>(fs, Wk, c, a);
            #pragma unroll
            for (int r = 0; r < 16; ++r) ksm[r * DD + c] = a[r];
        }
        {
            float a[16];
            #pragma unroll
            for (int r = 0; r < 16; ++r) a[r] = 0.f;
            gemm16<DD, DD>(fs, Wv, c, a);
            #pragma unroll
            for (int r = 0; r < 16; ++r) vsm[r * DD + c] = a[r];
        }
        __syncthreads();

        // attention: thread -> (head h, query q)
        {
            int hh = c >> 4;
            int qq = c & 15;
            float qreg[16];
            #pragma unroll
            for (int d = 0; d < 16; ++d) qreg[d] = qs[qq * DD + hh * 16 + d];
            float sc[16];
            #pragma unroll
            for (int k = 0; k < 16; ++k){
                float s = 0.f;
                #pragma unroll
                for (int d = 0; d < 16; ++d)
                    s = fmaf(qreg[d], ksm[k * DD + hh * 16 + d], s);
                sc[k] = s * 0.25f;   // 1/sqrt(16)
            }
            float m = sc[0];
            #pragma unroll
            for (int k = 1; k < 16; ++k) m = fmaxf(m, sc[k]);
            float den = 0.f;
            #pragma unroll
            for (int k = 0; k < 16; ++k){ sc[k] = expf(sc[k] - m); den += sc[k]; }
            float inv = 1.f / den;
            #pragma unroll
            for (int dv = 0; dv < 16; ++dv){
                float o = 0.f;
                #pragma unroll
                for (int k = 0; k < 16; ++k)
                    o = fmaf(sc[k], vsm[k * DD + hh * 16 + dv], o);
                tmp[qq * DD + hh * 16 + dv] = o * inv;
            }
        }
        __syncthreads();

        // attn proj + bias + residual + LayerNorm
        {
            float a[16];
            float b = attn_fc_b[layer * DD + c];
            #pragma unroll
            for (int r = 0; r < 16; ++r) a[r] = b;
            gemm16<DD, DD>(tmp, attn_fc_w + layer * DD * DD, c, a);
            #pragma unroll
            for (int r = 0; r < 16; ++r) a[r] += fs[r * DD + c];
            ln16(fs, a, c, attn_ln_g + layer * DD, attn_ln_b + layer * DD,
                 part_s, part_s2, mean_s, rstd_s);
        }

        // FFN: hid = relu(f@W1+b1) [16,512]; f = LN(hid@W2+b2+f)
        {
            #pragma unroll 1
            for (int cb = 0; cb < 4; ++cb){
                int col = cb * 128 + c;
                float a[16];
                float b1 = ffn_b1[layer * DFFC + col];
                #pragma unroll
                for (int r = 0; r < 16; ++r) a[r] = b1;
                gemm16<DD, DFFC>(fs, ffn_w1 + layer * DD * DFFC, col, a);
                #pragma unroll
                for (int r = 0; r < 16; ++r) big[r * DFFC + col] = fmaxf(a[r], 0.f);
            }
            __syncthreads();

            float a[16];
            float b2 = ffn_b2[layer * DD + c];
            #pragma unroll
            for (int r = 0; r < 16; ++r) a[r] = b2;
            gemm16<DFFC, DD>(big, ffn_w2 + layer * DFFC * DD, c, a);
            #pragma unroll
            for (int r = 0; r < 16; ++r) a[r] += fs[r * DD + c];
            ln16(fs, a, c, ffn_ln_g + layer * DD, ffn_ln_b + layer * DD,
                 part_s, part_s2, mean_s, rstd_s);
        }
    }

    // ---- pool over K, final projection + gelu + residual + final LN ----
    {
        float p = 0.f;
        #pragma unroll
        for (int r = 0; r < 16; ++r) p += fs[r * DD + c];
        pool[c] = p * (1.f / 16.f);
    }
    __syncthreads();
    {
        float acc = f2n_b[c];
        #pragma unroll 8
        for (int d = 0; d < DD; ++d)
            acc = fmaf(pool[d], __ldg(f2n_w + d * DD + c), acc);
        float y = gelu_tanh(acc) + node_h[(size_t)n * DD + c];

        float s = y, s2 = y * y;
        #pragma unroll
        for (int off = 16; off; off >>= 1){
            s  += __shfl_xor_sync(0xffffffffu, s,  off);
            s2 += __shfl_xor_sync(0xffffffffu, s2, off);
        }
        int w = c >> 5;
        if ((c & 31) == 0){ red[w] = s; red[4 + w] = s2; }
        __syncthreads();
        float sum  = red[0] + red[1] + red[2] + red[3];
        float sum2 = red[4] + red[5] + red[6] + red[7];
        float mean = sum * (1.f / 128.f);
        float var  = sum2 * (1.f / 128.f) - mean * mean;
        float rstd = rsqrtf(var + 1e-5f);
        out[(size_t)n * DD + c] = (y - mean) * rstd * fin_g[c] + fin_b[c];
    }
}

extern "C" void kernel_launch(void* const* d_in, const int* in_sizes, int n_in,
                              void* d_out, int out_size)
{
    const float* node_h     = (const float*)d_in[0];
    const int*   src_idx    = (const int*)  d_in[1];
    const float* edge_feat  = (const float*)d_in[2];
    const float* t_in       = (const float*)d_in[3];
    const float* t_now      = (const float*)d_in[4];
    const float* edge_fc_w  = (const float*)d_in[5];
    const float* edge_fc_b  = (const float*)d_in[6];
    const float* basis_freq = (const float*)d_in[7];
    const float* phase      = (const float*)d_in[8];
    const float* wq         = (const float*)d_in[9];
    const float* wk         = (const float*)d_in[10];
    const float* wv         = (const float*)d_in[11];
    const float* attn_fc_w  = (const float*)d_in[12];
    const float* attn_fc_b  = (const float*)d_in[13];
    const float* attn_ln_g  = (const float*)d_in[14];
    const float* attn_ln_b  = (const float*)d_in[15];
    const float* ffn_w1     = (const float*)d_in[16];
    const float* ffn_b1     = (const float*)d_in[17];
    const float* ffn_w2     = (const float*)d_in[18];
    const float* ffn_b2     = (const float*)d_in[19];
    const float* ffn_ln_g   = (const float*)d_in[20];
    const float* ffn_ln_b   = (const float*)d_in[21];
    const float* f2n_w      = (const float*)d_in[22];
    const float* f2n_b      = (const float*)d_in[23];
    const float* fin_g      = (const float*)d_in[24];
    const float* fin_b      = (const float*)d_in[25];
    float* out = (float*)d_out;

    tgn_fused_kernel<<<NN, 128>>>(node_h, src_idx, edge_feat, t_in, t_now,
                                  edge_fc_w, edge_fc_b, basis_freq, phase,
                                  wq, wk, wv, attn_fc_w, attn_fc_b, attn_ln_g, attn_ln_b,
                                  ffn_w1, ffn_b1, ffn_w2, ffn_b2, ffn_ln_g, ffn_ln_b,
                                  f2n_w, f2n_b, fin_g, fin_b, out);
}

// round 9
// speedup vs baseline: 1.3329x; 1.3329x over previous
#include <cuda_runtime.h>
#include <math.h>

#define KN   16
#define DD   128
#define LL   2
#define EE   32
#define DFFC 512

// two nodes per CTA, 64 threads (2 warps) per node, 2 columns per thread
#define NODE_F    9088            // floats per node smem region (16B-aligned total)
#define OFF_FS    0               // [16][128] mailbox f
#define OFF_Q     2048            // [16][128] q, later attn-out (in place)
#define OFF_K     4096            // [16][128] k, later FFN hidden chunk
#define OFF_V     6144            // [16][128] v, later FFN2 partial accum
#define OFF_EF    8192            // [16][32] edge features
#define OFF_PART  8704            // 32 : LN partial sums  (r*2 + warp)
#define OFF_PART2 8736            // 32 : LN partial sumsq
#define OFF_POOL  8768            // 128
#define OFF_T     8896            // 16
#define OFF_SRC   8912            // 16 (int)
#define OFF_RED   8928            // 4

typedef unsigned long long ull;

// ---------- packed f32x2 helpers ----------
__device__ __forceinline__ ull pk2(float lo, float hi){
    ull r; asm("mov.b64 %0, {%1, %2};" : "=l"(r) : "f"(lo), "f"(hi)); return r;
}
__device__ __forceinline__ void upk2(ull v, float& lo, float& hi){
    asm("mov.b64 {%0, %1}, %2;" : "=f"(lo), "=f"(hi) : "l"(v));
}
__device__ __forceinline__ ull fma2(ull a, ull b, ull c){
    ull d; asm("fma.rn.f32x2 %0, %1, %2, %3;" : "=l"(d) : "l"(a), "l"(b), "l"(c)); return d;
}

__device__ __forceinline__ float gelu_tanh(float x){
    float u = 0.7978845608028654f * fmaf(0.044715f * x, x * x, x);
    return 0.5f * x * (1.0f + tanhf(u));
}

// accA/accB (even/odd-d packed) += A[16][DIN](smem) @ W[DIN][Cs] columns c0, c0+1.
// W must already be offset to column c0. One LDS.128 feeds 4 FFMA2 (2 cols).
template<int DIN>
__device__ __forceinline__ void gemm16x2(const float* A, const float* __restrict__ W,
                                         int Cs, ull accA[16], ull accB[16]){
    const ulonglong2* A2 = reinterpret_cast<const ulonglong2*>(A);
    float2 f0 = __ldg((const float2*)(W));
    float2 f1 = __ldg((const float2*)(W + Cs));
    float2 f2 = __ldg((const float2*)(W + 2 * Cs));
    float2 f3 = __ldg((const float2*)(W + 3 * Cs));
    #pragma unroll 1
    for (int d4 = 0; d4 < DIN / 4; ++d4){
        ull wA0 = pk2(f0.x, f1.x), wA1 = pk2(f2.x, f3.x);
        ull wB0 = pk2(f0.y, f1.y), wB1 = pk2(f2.y, f3.y);
        if (d4 + 1 < DIN / 4){
            const float* Wn = W + (d4 + 1) * 4 * Cs;
            f0 = __ldg((const float2*)(Wn));
            f1 = __ldg((const float2*)(Wn + Cs));
            f2 = __ldg((const float2*)(Wn + 2 * Cs));
            f3 = __ldg((const float2*)(Wn + 3 * Cs));
        }
        #pragma unroll
        for (int r = 0; r < 16; ++r){
            ulonglong2 fv = A2[r * (DIN / 4) + d4];   // 4 d-values, broadcast LDS.128
            accA[r] = fma2(fv.x, wA0, accA[r]);
            accA[r] = fma2(fv.y, wA1, accA[r]);
            accB[r] = fma2(fv.x, wB0, accB[r]);
            accB[r] = fma2(fv.y, wB1, accB[r]);
        }
    }
}

// LayerNorm over 128 cols of 16 rows; 64 threads per node, a[r] = this thread's 2 cols.
// Writes normalized result into node's fs. Called by ALL 128 threads.
__device__ __forceinline__ void ln64(float2 a[16], float* Sn, int u,
                                     const float* __restrict__ g,
                                     const float* __restrict__ b, int c0){
    float* part  = Sn + OFF_PART;
    float* part2 = Sn + OFF_PART2;
    int w = u >> 5, lane = u & 31;
    #pragma unroll
    for (int r = 0; r < 16; ++r){
        float s  = a[r].x + a[r].y;
        float s2 = a[r].x * a[r].x + a[r].y * a[r].y;
        #pragma unroll
        for (int off = 16; off; off >>= 1){
            s  += __shfl_xor_sync(0xffffffffu, s,  off);
            s2 += __shfl_xor_sync(0xffffffffu, s2, off);
        }
        if (lane == 0){ part[r * 2 + w] = s; part2[r * 2 + w] = s2; }
    }
    __syncthreads();
    float2 gc = __ldg((const float2*)(g + c0));
    float2 bc = __ldg((const float2*)(b + c0));
    #pragma unroll
    for (int r = 0; r < 16; ++r){
        float su  = part[r * 2] + part[r * 2 + 1];
        float su2 = part2[r * 2] + part2[r * 2 + 1];
        float mean = su * (1.f / 128.f);
        float var  = su2 * (1.f / 128.f) - mean * mean;
        float rs   = rsqrtf(var + 1e-5f);
        float2 o;
        o.x = (a[r].x - mean) * rs * gc.x + bc.x;
        o.y = (a[r].y - mean) * rs * gc.y + bc.y;
        *(float2*)(Sn + OFF_FS + r * DD + c0) = o;
    }
    __syncthreads();
}

__global__ __launch_bounds__(128, 3)
void tgn2_kernel(
    const float* __restrict__ node_h,   const int*   __restrict__ src_idx,
    const float* __restrict__ edge_feat,const float* __restrict__ t_in,
    const float* __restrict__ t_now,
    const float* __restrict__ edge_fc_w,const float* __restrict__ edge_fc_b,
    const float* __restrict__ basis_freq,const float* __restrict__ phase,
    const float* __restrict__ wq, const float* __restrict__ wk, const float* __restrict__ wv,
    const float* __restrict__ attn_fc_w, const float* __restrict__ attn_fc_b,
    const float* __restrict__ attn_ln_g, const float* __restrict__ attn_ln_b,
    const float* __restrict__ ffn_w1, const float* __restrict__ ffn_b1,
    const float* __restrict__ ffn_w2, const float* __restrict__ ffn_b2,
    const float* __restrict__ ffn_ln_g, const float* __restrict__ ffn_ln_b,
    const float* __restrict__ f2n_w, const float* __restrict__ f2n_b,
    const float* __restrict__ fin_g, const float* __restrict__ fin_b,
    float* __restrict__ out)
{
    extern __shared__ __align__(16) float S[];
    const int tid = threadIdx.x;
    const int nl  = tid >> 6;                 // node within CTA (0/1)
    const int u   = tid & 63;                 // thread within node
    const int n   = (blockIdx.x << 1) + nl;
    float* Sn = S + nl * NODE_F;
    const int c0 = u << 1;                    // columns c0, c0+1

    // ---- stage edge features / t / src ----
    {
        const float* efg = edge_feat + (size_t)n * (KN * EE);
        #pragma unroll
        for (int j = 0; j < 8; ++j) Sn[OFF_EF + u + j * 64] = efg[u + j * 64];
        if (u < KN){
            Sn[OFF_T + u] = t_in[n * KN + u];
            ((int*)(Sn + OFF_SRC))[u] = src_idx[n * KN + u];
        }
    }
    __syncthreads();

    // ---- message: z = node_h[src] + gelu(edge@W+b) + cos((tnow-t)*freq + phase) ----
    {
        ull aA[16], aB[16];
        #pragma unroll
        for (int r = 0; r < 16; ++r){ aA[r] = 0ull; aB[r] = 0ull; }
        gemm16x2<EE>(Sn + OFF_EF, edge_fc_w + c0, DD, aA, aB);
        float2 eb = __ldg((const float2*)(edge_fc_b + c0));
        float2 fr = __ldg((const float2*)(basis_freq + c0));
        float2 ph = __ldg((const float2*)(phase + c0));
        float tn = t_now[0];
        #pragma unroll
        for (int r = 0; r < 16; ++r){
            float lo, hi; float2 g;
            upk2(aA[r], lo, hi); g.x = gelu_tanh(lo + hi + eb.x);
            upk2(aB[r], lo, hi); g.y = gelu_tanh(lo + hi + eb.y);
            float dt = tn - Sn[OFF_T + r];
            float tex = cosf(dt * fr.x + ph.x);
            float tey = cosf(dt * fr.y + ph.y);
            int sr = ((const int*)(Sn + OFF_SRC))[r];
            float2 nh = __ldg((const float2*)(node_h + (size_t)sr * DD + c0));
            *(float2*)(Sn + OFF_FS + r * DD + c0) =
                make_float2(nh.x + g.x + tex, nh.y + g.y + tey);
        }
    }
    __syncthreads();

    // ---- transformer layers ----
    #pragma unroll 1
    for (int layer = 0; layer < LL; ++layer){
        // QKV projections
        {
            ull aA[16], aB[16];
            #pragma unroll
            for (int r = 0; r < 16; ++r){ aA[r] = 0ull; aB[r] = 0ull; }
            gemm16x2<DD>(Sn + OFF_FS, wq + (size_t)layer * DD * DD + c0, DD, aA, aB);
            #pragma unroll
            for (int r = 0; r < 16; ++r){
                float lx, hx, ly, hy; upk2(aA[r], lx, hx); upk2(aB[r], ly, hy);
                *(float2*)(Sn + OFF_Q + r * DD + c0) = make_float2(lx + hx, ly + hy);
            }
        }
        {
            ull aA[16], aB[16];
            #pragma unroll
            for (int r = 0; r < 16; ++r){ aA[r] = 0ull; aB[r] = 0ull; }
            gemm16x2<DD>(Sn + OFF_FS, wk + (size_t)layer * DD * DD + c0, DD, aA, aB);
            #pragma unroll
            for (int r = 0; r < 16; ++r){
                float lx, hx, ly, hy; upk2(aA[r], lx, hx); upk2(aB[r], ly, hy);
                *(float2*)(Sn + OFF_K + r * DD + c0) = make_float2(lx + hx, ly + hy);
            }
        }
        {
            ull aA[16], aB[16];
            #pragma unroll
            for (int r = 0; r < 16; ++r){ aA[r] = 0ull; aB[r] = 0ull; }
            gemm16x2<DD>(Sn + OFF_FS, wv + (size_t)layer * DD * DD + c0, DD, aA, aB);
            #pragma unroll
            for (int r = 0; r < 16; ++r){
                float lx, hx, ly, hy; upk2(aA[r], lx, hx); upk2(aB[r], ly, hy);
                *(float2*)(Sn + OFF_V + r * DD + c0) = make_float2(lx + hx, ly + hy);
            }
        }
        __syncthreads();

        // attention: thread -> head h = u/8, two queries; attn-out overwrites q in place
        {
            const int h  = u >> 3;
            const int qb = (u & 7) << 1;
            float* qsm = Sn + OFF_Q;
            float* ksm = Sn + OFF_K;
            float* vsm = Sn + OFF_V;
            #pragma unroll
            for (int qi = 0; qi < 2; ++qi){
                int qq = qb + qi;
                float qreg[16];
                #pragma unroll
                for (int d = 0; d < 16; ++d) qreg[d] = qsm[qq * DD + h * 16 + d];
                float sc[16];
                #pragma unroll
                for (int k = 0; k < 16; ++k){
                    float s = 0.f;
                    #pragma unroll
                    for (int d = 0; d < 16; ++d)
                        s = fmaf(qreg[d], ksm[k * DD + h * 16 + d], s);
                    sc[k] = s * 0.25f;
                }
                float m = sc[0];
                #pragma unroll
                for (int k = 1; k < 16; ++k) m = fmaxf(m, sc[k]);
                float den = 0.f;
                #pragma unroll
                for (int k = 0; k < 16; ++k){ sc[k] = expf(sc[k] - m); den += sc[k]; }
                float inv = 1.f / den;
                #pragma unroll
                for (int dv = 0; dv < 16; ++dv){
                    float o = 0.f;
                    #pragma unroll
                    for (int k = 0; k < 16; ++k)
                        o = fmaf(sc[k], vsm[k * DD + h * 16 + dv], o);
                    qsm[qq * DD + h * 16 + dv] = o * inv;   // own block only
                }
            }
        }
        __syncthreads();

        // attn proj + bias + residual + LN
        {
            ull aA[16], aB[16];
            #pragma unroll
            for (int r = 0; r < 16; ++r){ aA[r] = 0ull; aB[r] = 0ull; }
            gemm16x2<DD>(Sn + OFF_Q, attn_fc_w + (size_t)layer * DD * DD + c0, DD, aA, aB);
            float2 bb = __ldg((const float2*)(attn_fc_b + layer * DD + c0));
            float2 a[16];
            #pragma unroll
            for (int r = 0; r < 16; ++r){
                float lx, hx, ly, hy; upk2(aA[r], lx, hx); upk2(aB[r], ly, hy);
                float2 fv = *(float2*)(Sn + OFF_FS + r * DD + c0);
                a[r] = make_float2(lx + hx + bb.x + fv.x, ly + hy + bb.y + fv.y);
            }
            ln64(a, Sn, u, attn_ln_g + layer * DD, attn_ln_b + layer * DD, c0);
        }

        // FFN: hidden chunked 4x128 through K region; partial out accumulated in V region
        {
            float2 b2 = __ldg((const float2*)(ffn_b2 + layer * DD + c0));
            #pragma unroll
            for (int r = 0; r < 16; ++r)
                *(float2*)(Sn + OFF_V + r * DD + c0) = b2;   // own slots
            __syncthreads();
            #pragma unroll 1
            for (int cb = 0; cb < 4; ++cb){
                ull hA[16], hB[16];
                #pragma unroll
                for (int r = 0; r < 16; ++r){ hA[r] = 0ull; hB[r] = 0ull; }
                gemm16x2<DD>(Sn + OFF_FS,
                             ffn_w1 + (size_t)layer * DD * DFFC + cb * 128 + c0,
                             DFFC, hA, hB);
                float2 b1 = __ldg((const float2*)(ffn_b1 + layer * DFFC + cb * 128 + c0));
                #pragma unroll
                for (int r = 0; r < 16; ++r){
                    float lx, hx, ly, hy; upk2(hA[r], lx, hx); upk2(hB[r], ly, hy);
                    *(float2*)(Sn + OFF_K + r * DD + c0) =
                        make_float2(fmaxf(lx + hx + b1.x, 0.f), fmaxf(ly + hy + b1.y, 0.f));
                }
                __syncthreads();
                ull oA[16], oB[16];
                #pragma unroll
                for (int r = 0; r < 16; ++r){ oA[r] = 0ull; oB[r] = 0ull; }
                gemm16x2<DD>(Sn + OFF_K,
                             ffn_w2 + (size_t)layer * DFFC * DD + (size_t)cb * 128 * DD + c0,
                             DD, oA, oB);
                #pragma unroll
                for (int r = 0; r < 16; ++r){
                    float lx, hx, ly, hy; upk2(oA[r], lx, hx); upk2(oB[r], ly, hy);
                    float2 ov = *(float2*)(Sn + OFF_V + r * DD + c0);
                    *(float2*)(Sn + OFF_V + r * DD + c0) =
                        make_float2(ov.x + lx + hx, ov.y + ly + hy);
                }
                __syncthreads();
            }
            float2 a[16];
            #pragma unroll
            for (int r = 0; r < 16; ++r){
                float2 ov = *(float2*)(Sn + OFF_V + r * DD + c0);
                float2 fv = *(float2*)(Sn + OFF_FS + r * DD + c0);
                a[r] = make_float2(ov.x + fv.x, ov.y + fv.y);
            }
            ln64(a, Sn, u, ffn_ln_g + layer * DD, ffn_ln_b + layer * DD, c0);
        }
    }

    // ---- pool, final projection + gelu + residual + final LN ----
    {
        float2 p = make_float2(0.f, 0.f);
        #pragma unroll
        for (int r = 0; r < 16; ++r){
            float2 fv = *(float2*)(Sn + OFF_FS + r * DD + c0);
            p.x += fv.x; p.y += fv.y;
        }
        *(float2*)(Sn + OFF_POOL + c0) = make_float2(p.x * (1.f / 16.f), p.y * (1.f / 16.f));
    }
    __syncthreads();
    {
        float2 acc = __ldg((const float2*)(f2n_b + c0));
        const float* pool = Sn + OFF_POOL;
        #pragma unroll 4
        for (int d = 0; d < DD; ++d){
            float pd = pool[d];
            float2 w2 = __ldg((const float2*)(f2n_w + d * DD + c0));
            acc.x = fmaf(pd, w2.x, acc.x);
            acc.y = fmaf(pd, w2.y, acc.y);
        }
        float2 nh = __ldg((const float2*)(node_h + (size_t)n * DD + c0));
        float2 y = make_float2(gelu_tanh(acc.x) + nh.x, gelu_tanh(acc.y) + nh.y);

        float s = y.x + y.y, s2 = y.x * y.x + y.y * y.y;
        #pragma unroll
        for (int off = 16; off; off >>= 1){
            s  += __shfl_xor_sync(0xffffffffu, s,  off);
            s2 += __shfl_xor_sync(0xffffffffu, s2, off);
        }
        int w = u >> 5, lane = u & 31;
        if (lane == 0){ Sn[OFF_RED + w] = s; Sn[OFF_RED + 2 + w] = s2; }
        __syncthreads();
        float su  = Sn[OFF_RED] + Sn[OFF_RED + 1];
        float su2 = Sn[OFF_RED + 2] + Sn[OFF_RED + 3];
        float mean = su * (1.f / 128.f);
        float var  = su2 * (1.f / 128.f) - mean * mean;
        float rs   = rsqrtf(var + 1e-5f);
        float2 g = __ldg((const float2*)(fin_g + c0));
        float2 b = __ldg((const float2*)(fin_b + c0));
        *(float2*)(out + (size_t)n * DD + c0) =
            make_float2((y.x - mean) * rs * g.x + b.x, (y.y - mean) * rs * g.y + b.y);
    }
}

extern "C" void kernel_launch(void* const* d_in, const int* in_sizes, int n_in,
                              void* d_out, int out_size)
{
    const float* node_h     = (const float*)d_in[0];
    const int*   src_idx    = (const int*)  d_in[1];
    const float* edge_feat  = (const float*)d_in[2];
    const float* t_in       = (const float*)d_in[3];
    const float* t_now      = (const float*)d_in[4];
    const float* edge_fc_w  = (const float*)d_in[5];
    const float* edge_fc_b  = (const float*)d_in[6];
    const float* basis_freq = (const float*)d_in[7];
    const float* phase      = (const float*)d_in[8];
    const float* wq         = (const float*)d_in[9];
    const float* wk         = (const float*)d_in[10];
    const float* wv         = (const float*)d_in[11];
    const float* attn_fc_w  = (const float*)d_in[12];
    const float* attn_fc_b  = (const float*)d_in[13];
    const float* attn_ln_g  = (const float*)d_in[14];
    const float* attn_ln_b  = (const float*)d_in[15];
    const float* ffn_w1     = (const float*)d_in[16];
    const float* ffn_b1     = (const float*)d_in[17];
    const float* ffn_w2     = (const float*)d_in[18];
    const float* ffn_b2     = (const float*)d_in[19];
    const float* ffn_ln_g   = (const float*)d_in[20];
    const float* ffn_ln_b   = (const float*)d_in[21];
    const float* f2n_w      = (const float*)d_in[22];
    const float* f2n_b      = (const float*)d_in[23];
    const float* fin_g      = (const float*)d_in[24];
    const float* fin_b      = (const float*)d_in[25];
    float* out = (float*)d_out;

    const int smem_bytes = 2 * NODE_F * (int)sizeof(float);   // 72704
    cudaFuncSetAttribute(tgn2_kernel, cudaFuncAttributeMaxDynamicSharedMemorySize, smem_bytes);

    tgn2_kernel<<<8192, 128, smem_bytes>>>(node_h, src_idx, edge_feat, t_in, t_now,
                                  edge_fc_w, edge_fc_b, basis_freq, phase,
                                  wq, wk, wv, attn_fc_w, attn_fc_b, attn_ln_g, attn_ln_b,
                                  ffn_w1, ffn_b1, ffn_w2, ffn_b2, ffn_ln_g, ffn_ln_b,
                                  f2n_w, f2n_b, fin_g, fin_b, out);
}

// round 10
// speedup vs baseline: 1.4022x; 1.0520x over previous
#include <cuda_runtime.h>
#include <math.h>

#define KN   16
#define DD   128
#define LL   2
#define EE   32
#define DFFC 512

#define NODE_F    9088
#define OFF_FS    0
#define OFF_Q     2048
#define OFF_K     4096
#define OFF_V     6144
#define OFF_EF    8192
#define OFF_PART  8704
#define OFF_PART2 8736
#define OFF_POOL  8768
#define OFF_T     8896
#define OFF_SRC   8912
#define OFF_RED   8928

typedef unsigned long long ull;

#define NBAR(id) asm volatile("bar.sync %0, 64;" :: "r"(id) : "memory")

__device__ __forceinline__ ull pk2(float lo, float hi){
    ull r; asm("mov.b64 %0, {%1, %2};" : "=l"(r) : "f"(lo), "f"(hi)); return r;
}
__device__ __forceinline__ void upk2(ull v, float& lo, float& hi){
    asm("mov.b64 {%0, %1}, %2;" : "=f"(lo), "=f"(hi) : "l"(v));
}
__device__ __forceinline__ ull fma2(ull a, ull b, ull c){
    ull d; asm("fma.rn.f32x2 %0, %1, %2, %3;" : "=l"(d) : "l"(a), "l"(b), "l"(c)); return d;
}

// gelu(x) = x * sigmoid(2*0.79788456*(x + 0.044715 x^3)), fast-exp version
__device__ __forceinline__ float gelu_fast(float x){
    float u2 = 1.5957691216057308f * fmaf(0.044715f * x, x * x, x);
    u2 = fminf(fmaxf(u2, -80.f), 80.f);
    float a = __expf(u2);
    return x * __fdividef(a, a + 1.f);
}

// accA/accB += A[16][DIN](smem) @ W[DIN][Cs] columns c0, c0+1 (even/odd-d packed)
template<int DIN>
__device__ __forceinline__ void gemm16x2(const float* A, const float* __restrict__ W,
                                         int Cs, ull accA[16], ull accB[16]){
    const ulonglong2* A2 = reinterpret_cast<const ulonglong2*>(A);
    float2 f0 = __ldg((const float2*)(W));
    float2 f1 = __ldg((const float2*)(W + Cs));
    float2 f2 = __ldg((const float2*)(W + 2 * Cs));
    float2 f3 = __ldg((const float2*)(W + 3 * Cs));
    #pragma unroll 1
    for (int d4 = 0; d4 < DIN / 4; ++d4){
        ull wA0 = pk2(f0.x, f1.x), wA1 = pk2(f2.x, f3.x);
        ull wB0 = pk2(f0.y, f1.y), wB1 = pk2(f2.y, f3.y);
        if (d4 + 1 < DIN / 4){
            const float* Wn = W + (d4 + 1) * 4 * Cs;
            f0 = __ldg((const float2*)(Wn));
            f1 = __ldg((const float2*)(Wn + Cs));
            f2 = __ldg((const float2*)(Wn + 2 * Cs));
            f3 = __ldg((const float2*)(Wn + 3 * Cs));
        }
        #pragma unroll
        for (int r = 0; r < 16; ++r){
            ulonglong2 fv = A2[r * (DIN / 4) + d4];
            accA[r] = fma2(fv.x, wA0, accA[r]);
            accA[r] = fma2(fv.y, wA1, accA[r]);
            accB[r] = fma2(fv.x, wB0, accB[r]);
            accB[r] = fma2(fv.y, wB1, accB[r]);
        }
    }
}

// LayerNorm over 128 cols of 16 rows; per-node (64 threads, named barrier bid)
__device__ __forceinline__ void ln64(float2 a[16], float* Sn, int u, int bid,
                                     const float* __restrict__ g,
                                     const float* __restrict__ b, int c0){
    float* part  = Sn + OFF_PART;
    float* part2 = Sn + OFF_PART2;
    int w = u >> 5, lane = u & 31;
    #pragma unroll
    for (int r = 0; r < 16; ++r){
        float s  = a[r].x + a[r].y;
        float s2 = a[r].x * a[r].x + a[r].y * a[r].y;
        #pragma unroll
        for (int off = 16; off; off >>= 1){
            s  += __shfl_xor_sync(0xffffffffu, s,  off);
            s2 += __shfl_xor_sync(0xffffffffu, s2, off);
        }
        if (lane == 0){ part[r * 2 + w] = s; part2[r * 2 + w] = s2; }
    }
    NBAR(bid);
    float2 gc = __ldg((const float2*)(g + c0));
    float2 bc = __ldg((const float2*)(b + c0));
    #pragma unroll
    for (int r = 0; r < 16; ++r){
        float su  = part[r * 2] + part[r * 2 + 1];
        float su2 = part2[r * 2] + part2[r * 2 + 1];
        float mean = su * (1.f / 128.f);
        float var  = su2 * (1.f / 128.f) - mean * mean;
        float rs   = rsqrtf(var + 1e-5f);
        float2 o;
        o.x = (a[r].x - mean) * rs * gc.x + bc.x;
        o.y = (a[r].y - mean) * rs * gc.y + bc.y;
        *(float2*)(Sn + OFF_FS + r * DD + c0) = o;
    }
    NBAR(bid);
}

__global__ __launch_bounds__(128, 3)
void tgn3_kernel(
    const float* __restrict__ node_h,   const int*   __restrict__ src_idx,
    const float* __restrict__ edge_feat,const float* __restrict__ t_in,
    const float* __restrict__ t_now,
    const float* __restrict__ edge_fc_w,const float* __restrict__ edge_fc_b,
    const float* __restrict__ basis_freq,const float* __restrict__ phase,
    const float* __restrict__ wq, const float* __restrict__ wk, const float* __restrict__ wv,
    const float* __restrict__ attn_fc_w, const float* __restrict__ attn_fc_b,
    const float* __restrict__ attn_ln_g, const float* __restrict__ attn_ln_b,
    const float* __restrict__ ffn_w1, const float* __restrict__ ffn_b1,
    const float* __restrict__ ffn_w2, const float* __restrict__ ffn_b2,
    const float* __restrict__ ffn_ln_g, const float* __restrict__ ffn_ln_b,
    const float* __restrict__ f2n_w, const float* __restrict__ f2n_b,
    const float* __restrict__ fin_g, const float* __restrict__ fin_b,
    float* __restrict__ out)
{
    extern __shared__ __align__(16) float S[];
    const int tid = threadIdx.x;
    const int nl  = tid >> 6;
    const int u   = tid & 63;
    const int n   = (blockIdx.x << 1) + nl;
    const int bid = nl + 1;                  // named barrier id (1 or 2)
    float* Sn = S + nl * NODE_F;
    const int c0 = u << 1;

    // ---- stage ----
    {
        const float* efg = edge_feat + (size_t)n * (KN * EE);
        #pragma unroll
        for (int j = 0; j < 8; ++j) Sn[OFF_EF + u + j * 64] = efg[u + j * 64];
        if (u < KN){
            Sn[OFF_T + u] = t_in[n * KN + u];
            ((int*)(Sn + OFF_SRC))[u] = src_idx[n * KN + u];
        }
    }
    NBAR(bid);

    // ---- message ----
    {
        ull aA[16], aB[16];
        #pragma unroll
        for (int r = 0; r < 16; ++r){ aA[r] = 0ull; aB[r] = 0ull; }
        gemm16x2<EE>(Sn + OFF_EF, edge_fc_w + c0, DD, aA, aB);
        float2 eb = __ldg((const float2*)(edge_fc_b + c0));
        float2 fr = __ldg((const float2*)(basis_freq + c0));
        float2 ph = __ldg((const float2*)(phase + c0));
        float tn = t_now[0];
        #pragma unroll
        for (int r = 0; r < 16; ++r){
            float lo, hi; float2 g;
            upk2(aA[r], lo, hi); g.x = gelu_fast(lo + hi + eb.x);
            upk2(aB[r], lo, hi); g.y = gelu_fast(lo + hi + eb.y);
            float dt = tn - Sn[OFF_T + r];
            float tex = __cosf(dt * fr.x + ph.x);
            float tey = __cosf(dt * fr.y + ph.y);
            int sr = ((const int*)(Sn + OFF_SRC))[r];
            float2 nh = __ldg((const float2*)(node_h + (size_t)sr * DD + c0));
            *(float2*)(Sn + OFF_FS + r * DD + c0) =
                make_float2(nh.x + g.x + tex, nh.y + g.y + tey);
        }
    }
    NBAR(bid);

    // ---- transformer layers ----
    #pragma unroll 1
    for (int layer = 0; layer < LL; ++layer){
        {
            ull aA[16], aB[16];
            #pragma unroll
            for (int r = 0; r < 16; ++r){ aA[r] = 0ull; aB[r] = 0ull; }
            gemm16x2<DD>(Sn + OFF_FS, wq + (size_t)layer * DD * DD + c0, DD, aA, aB);
            #pragma unroll
            for (int r = 0; r < 16; ++r){
                float lx, hx, ly, hy; upk2(aA[r], lx, hx); upk2(aB[r], ly, hy);
                *(float2*)(Sn + OFF_Q + r * DD + c0) = make_float2(lx + hx, ly + hy);
            }
        }
        {
            ull aA[16], aB[16];
            #pragma unroll
            for (int r = 0; r < 16; ++r){ aA[r] = 0ull; aB[r] = 0ull; }
            gemm16x2<DD>(Sn + OFF_FS, wk + (size_t)layer * DD * DD + c0, DD, aA, aB);
            #pragma unroll
            for (int r = 0; r < 16; ++r){
                float lx, hx, ly, hy; upk2(aA[r], lx, hx); upk2(aB[r], ly, hy);
                *(float2*)(Sn + OFF_K + r * DD + c0) = make_float2(lx + hx, ly + hy);
            }
        }
        {
            ull aA[16], aB[16];
            #pragma unroll
            for (int r = 0; r < 16; ++r){ aA[r] = 0ull; aB[r] = 0ull; }
            gemm16x2<DD>(Sn + OFF_FS, wv + (size_t)layer * DD * DD + c0, DD, aA, aB);
            #pragma unroll
            for (int r = 0; r < 16; ++r){
                float lx, hx, ly, hy; upk2(aA[r], lx, hx); upk2(aB[r], ly, hy);
                *(float2*)(Sn + OFF_V + r * DD + c0) = make_float2(lx + hx, ly + hy);
            }
        }
        NBAR(bid);

        // attention (vectorized LDS.128 / fma2 scores / float4 V / STS.128)
        {
            const int h  = u >> 3;
            const int qb = (u & 7) << 1;
            float* qsm = Sn + OFF_Q;
            float* ksm = Sn + OFF_K;
            float* vsm = Sn + OFF_V;
            #pragma unroll
            for (int qi = 0; qi < 2; ++qi){
                int qq = qb + qi;
                const ulonglong2* qp = (const ulonglong2*)(qsm + qq * DD + h * 16);
                ulonglong2 q01 = qp[0], q23 = qp[1];   // 8 d-values as 4 ulls... need 16
                ulonglong2 q45 = qp[2], q67 = qp[3];
                float sc[16];
                #pragma unroll
                for (int k = 0; k < 16; ++k){
                    const ulonglong2* kp = (const ulonglong2*)(ksm + k * DD + h * 16);
                    ulonglong2 k01 = kp[0], k23 = kp[1], k45 = kp[2], k67 = kp[3];
                    ull acc = fma2(q01.x, k01.x, 0ull);
                    acc = fma2(q01.y, k01.y, acc);
                    acc = fma2(q23.x, k23.x, acc);
                    acc = fma2(q23.y, k23.y, acc);
                    acc = fma2(q45.x, k45.x, acc);
                    acc = fma2(q45.y, k45.y, acc);
                    acc = fma2(q67.x, k67.x, acc);
                    acc = fma2(q67.y, k67.y, acc);
                    float lo, hi; upk2(acc, lo, hi);
                    sc[k] = (lo + hi) * 0.25f;
                }
                float m = sc[0];
                #pragma unroll
                for (int k = 1; k < 16; ++k) m = fmaxf(m, sc[k]);
                float den = 0.f;
                #pragma unroll
                for (int k = 0; k < 16; ++k){ sc[k] = __expf(sc[k] - m); den += sc[k]; }
                float inv = __fdividef(1.f, den);
                #pragma unroll
                for (int c = 0; c < 4; ++c){
                    float4 o = make_float4(0.f, 0.f, 0.f, 0.f);
                    #pragma unroll
                    for (int k = 0; k < 16; ++k){
                        float4 v = *(const float4*)(vsm + k * DD + h * 16 + c * 4);
                        o.x = fmaf(sc[k], v.x, o.x);
                        o.y = fmaf(sc[k], v.y, o.y);
                        o.z = fmaf(sc[k], v.z, o.z);
                        o.w = fmaf(sc[k], v.w, o.w);
                    }
                    *(float4*)(qsm + qq * DD + h * 16 + c * 4) =
                        make_float4(o.x * inv, o.y * inv, o.z * inv, o.w * inv);
                }
            }
        }
        NBAR(bid);

        // attn proj + bias + residual + LN
        {
            ull aA[16], aB[16];
            #pragma unroll
            for (int r = 0; r < 16; ++r){ aA[r] = 0ull; aB[r] = 0ull; }
            gemm16x2<DD>(Sn + OFF_Q, attn_fc_w + (size_t)layer * DD * DD + c0, DD, aA, aB);
            float2 bb = __ldg((const float2*)(attn_fc_b + layer * DD + c0));
            float2 a[16];
            #pragma unroll
            for (int r = 0; r < 16; ++r){
                float lx, hx, ly, hy; upk2(aA[r], lx, hx); upk2(aB[r], ly, hy);
                float2 fv = *(float2*)(Sn + OFF_FS + r * DD + c0);
                a[r] = make_float2(lx + hx + bb.x + fv.x, ly + hy + bb.y + fv.y);
            }
            ln64(a, Sn, u, bid, attn_ln_g + layer * DD, attn_ln_b + layer * DD, c0);
        }

        // FFN
        {
            float2 b2 = __ldg((const float2*)(ffn_b2 + layer * DD + c0));
            #pragma unroll
            for (int r = 0; r < 16; ++r)
                *(float2*)(Sn + OFF_V + r * DD + c0) = b2;
            NBAR(bid);
            #pragma unroll 1
            for (int cb = 0; cb < 4; ++cb){
                ull hA[16], hB[16];
                #pragma unroll
                for (int r = 0; r < 16; ++r){ hA[r] = 0ull; hB[r] = 0ull; }
                gemm16x2<DD>(Sn + OFF_FS,
                             ffn_w1 + (size_t)layer * DD * DFFC + cb * 128 + c0,
                             DFFC, hA, hB);
                float2 b1 = __ldg((const float2*)(ffn_b1 + layer * DFFC + cb * 128 + c0));
                #pragma unroll
                for (int r = 0; r < 16; ++r){
                    float lx, hx, ly, hy; upk2(hA[r], lx, hx); upk2(hB[r], ly, hy);
                    *(float2*)(Sn + OFF_K + r * DD + c0) =
                        make_float2(fmaxf(lx + hx + b1.x, 0.f), fmaxf(ly + hy + b1.y, 0.f));
                }
                NBAR(bid);
                ull oA[16], oB[16];
                #pragma unroll
                for (int r = 0; r < 16; ++r){ oA[r] = 0ull; oB[r] = 0ull; }
                gemm16x2<DD>(Sn + OFF_K,
                             ffn_w2 + (size_t)layer * DFFC * DD + (size_t)cb * 128 * DD + c0,
                             DD, oA, oB);
                #pragma unroll
                for (int r = 0; r < 16; ++r){
                    float lx, hx, ly, hy; upk2(oA[r], lx, hx); upk2(oB[r], ly, hy);
                    float2 ov = *(float2*)(Sn + OFF_V + r * DD + c0);
                    *(float2*)(Sn + OFF_V + r * DD + c0) =
                        make_float2(ov.x + lx + hx, ov.y + ly + hy);
                }
                NBAR(bid);
            }
            float2 a[16];
            #pragma unroll
            for (int r = 0; r < 16; ++r){
                float2 ov = *(float2*)(Sn + OFF_V + r * DD + c0);
                float2 fv = *(float2*)(Sn + OFF_FS + r * DD + c0);
                a[r] = make_float2(ov.x + fv.x, ov.y + fv.y);
            }
            ln64(a, Sn, u, bid, ffn_ln_g + layer * DD, ffn_ln_b + layer * DD, c0);
        }
    }

    // ---- pool + final ----
    {
        float2 p = make_float2(0.f, 0.f);
        #pragma unroll
        for (int r = 0; r < 16; ++r){
            float2 fv = *(float2*)(Sn + OFF_FS + r * DD + c0);
            p.x += fv.x; p.y += fv.y;
        }
        *(float2*)(Sn + OFF_POOL + c0) = make_float2(p.x * (1.f / 16.f), p.y * (1.f / 16.f));
    }
    NBAR(bid);
    {
        float2 acc = __ldg((const float2*)(f2n_b + c0));
        const float* pool = Sn + OFF_POOL;
        #pragma unroll 4
        for (int d = 0; d < DD; ++d){
            float pd = pool[d];
            float2 w2 = __ldg((const float2*)(f2n_w + d * DD + c0));
            acc.x = fmaf(pd, w2.x, acc.x);
            acc.y = fmaf(pd, w2.y, acc.y);
        }
        float2 nh = __ldg((const float2*)(node_h + (size_t)n * DD + c0));
        float2 y = make_float2(gelu_fast(acc.x) + nh.x, gelu_fast(acc.y) + nh.y);

        float s = y.x + y.y, s2 = y.x * y.x + y.y * y.y;
        #pragma unroll
        for (int off = 16; off; off >>= 1){
            s  += __shfl_xor_sync(0xffffffffu, s,  off);
            s2 += __shfl_xor_sync(0xffffffffu, s2, off);
        }
        int w = u >> 5, lane = u & 31;
        if (lane == 0){ Sn[OFF_RED + w] = s; Sn[OFF_RED + 2 + w] = s2; }
        NBAR(bid);
        float su  = Sn[OFF_RED] + Sn[OFF_RED + 1];
        float su2 = Sn[OFF_RED + 2] + Sn[OFF_RED + 3];
        float mean = su * (1.f / 128.f);
        float var  = su2 * (1.f / 128.f) - mean * mean;
        float rs   = rsqrtf(var + 1e-5f);
        float2 g = __ldg((const float2*)(fin_g + c0));
        float2 b = __ldg((const float2*)(fin_b + c0));
        *(float2*)(out + (size_t)n * DD + c0) =
            make_float2((y.x - mean) * rs * g.x + b.x, (y.y - mean) * rs * g.y + b.y);
    }
}

extern "C" void kernel_launch(void* const* d_in, const int* in_sizes, int n_in,
                              void* d_out, int out_size)
{
    const float* node_h     = (const float*)d_in[0];
    const int*   src_idx    = (const int*)  d_in[1];
    const float* edge_feat  = (const float*)d_in[2];
    const float* t_in       = (const float*)d_in[3];
    const float* t_now      = (const float*)d_in[4];
    const float* edge_fc_w  = (const float*)d_in[5];
    const float* edge_fc_b  = (const float*)d_in[6];
    const float* basis_freq = (const float*)d_in[7];
    const float* phase      = (const float*)d_in[8];
    const float* wq         = (const float*)d_in[9];
    const float* wk         = (const float*)d_in[10];
    const float* wv         = (const float*)d_in[11];
    const float* attn_fc_w  = (const float*)d_in[12];
    const float* attn_fc_b  = (const float*)d_in[13];
    const float* attn_ln_g  = (const float*)d_in[14];
    const float* attn_ln_b  = (const float*)d_in[15];
    const float* ffn_w1     = (const float*)d_in[16];
    const float* ffn_b1     = (const float*)d_in[17];
    const float* ffn_w2     = (const float*)d_in[18];
    const float* ffn_b2     = (const float*)d_in[19];
    const float* ffn_ln_g   = (const float*)d_in[20];
    const float* ffn_ln_b   = (const float*)d_in[21];
    const float* f2n_w      = (const float*)d_in[22];
    const float* f2n_b      = (const float*)d_in[23];
    const float* fin_g      = (const float*)d_in[24];
    const float* fin_b      = (const float*)d_in[25];
    float* out = (float*)d_out;

    const int smem_bytes = 2 * NODE_F * (int)sizeof(float);   // 72704
    cudaFuncSetAttribute(tgn3_kernel, cudaFuncAttributeMaxDynamicSharedMemorySize, smem_bytes);

    tgn3_kernel<<<8192, 128, smem_bytes>>>(node_h, src_idx, edge_feat, t_in, t_now,
                                  edge_fc_w, edge_fc_b, basis_freq, phase,
                                  wq, wk, wv, attn_fc_w, attn_fc_b, attn_ln_g, attn_ln_b,
                                  ffn_w1, ffn_b1, ffn_w2, ffn_b2, ffn_ln_g, ffn_ln_b,
                                  f2n_w, f2n_b, fin_g, fin_b, out);
}